// round 17
// baseline (speedup 1.0000x reference)
#include <cuda_runtime.h>
#include <cstdint>

#define DD 1024
#define NB 16
#define NF 2080

typedef unsigned long long u64;

__device__ float2 g_H [(size_t)NB * DD * DD];          // Hermitianized rho
__device__ float2 g_H2[(size_t)NB * 64 * 32 * DD];     // [b][a][x][n]
__device__ float2 g_G [(size_t)NB * 64 * 64 * DD];     // [b][c][a][n]
__device__ int    g_pairs[NF];

// ---------------- f32x2 helpers ----------------------------------------------
__device__ __forceinline__ u64 pkf2(float a, float b) {
    u64 r; asm("mov.b64 %0, {%1, %2};" : "=l"(r) : "f"(a), "f"(b)); return r;
}
__device__ __forceinline__ float2 upk(u64 v) {
    float2 r; asm("mov.b64 {%0, %1}, %2;" : "=f"(r.x), "=f"(r.y) : "l"(v)); return r;
}
__device__ __forceinline__ u64 swp(u64 v) {
    u64 r;
    asm("{ .reg .f32 a, b;\n\t mov.b64 {a, b}, %1;\n\t mov.b64 %0, {b, a}; }"
        : "=l"(r) : "l"(v));
    return r;
}
__device__ __forceinline__ void fma2(u64& acc, u64 a, u64 b) {
    asm("fma.rn.f32x2 %0, %1, %2, %3;" : "=l"(acc) : "l"(a), "l"(b), "l"(acc));
}
// broadcast packs for complex mult by m: (m.x,m.x) and (-m.y,m.y)
__device__ __forceinline__ void cpack(float2 m, u64& xx, u64& ny) {
    xx = pkf2(m.x, m.x); ny = pkf2(-m.y, m.y);
}

__global__ void pairs_init() {
    int g = blockIdx.x * 256 + threadIdx.x;
    if (g < NF) {
        int j = 0, rem = g;
        while (rem >= 64 - j) { rem -= 64 - j; ++j; }
        g_pairs[g] = (j << 8) | (j + rem);
    }
}

// ---- Hermitianize rho upper triangle into g_H (float2) ----------------------
__global__ void pack_H(const float* __restrict__ rr, const float* __restrict__ ri) {
    int ti = blockIdx.x, tj = blockIdx.y, b = blockIdx.z;
    if (tj < ti) return;
    __shared__ float sr[32][33], si[32][33];
    int cx = threadIdx.x, ry = threadIdx.y;
    const size_t base = (size_t)b * DD * DD;
    int r = ti * 32 + ry, c = tj * 32 + cx;
    sr[ry][cx] = rr[base + (size_t)r * DD + c];
    si[ry][cx] = ri[base + (size_t)r * DD + c];
    __syncthreads();
    float2* H = g_H + base;
    if (ti == tj) {
        float2 v;
        if (ry < cx)      v = make_float2(sr[ry][cx], si[ry][cx]);
        else if (ry > cx) v = make_float2(sr[cx][ry], -si[cx][ry]);
        else              v = make_float2(sr[ry][cx], 0.f);
        H[(size_t)r * DD + c] = v;
    } else {
        H[(size_t)r * DD + c] = make_float2(sr[ry][cx], si[ry][cx]);
        int r2 = tj * 32 + ry, c2 = ti * 32 + cx;
        H[(size_t)r2 * DD + c2] = make_float2(sr[cx][ry], -si[cx][ry]);
    }
}

// ---- small-K GEMM: OUT[64,128] = M(64x32) * IN(32x128), f32x2 core ----------
template <int MODE>
__global__ void __launch_bounds__(256) s1_gemm(const float* __restrict__ U_re,
                                               const float* __restrict__ U_im) {
    const int nt = blockIdx.x, sl = blockIdx.y, b = blockIdx.z;
    __shared__ float2 sM[64][32];
    __shared__ float2 sIn[32][128];
    const int tid = threadIdx.x;
    const int mcol = (MODE == 1) ? 32 : 0;
#pragma unroll
    for (int i = 0; i < 8; ++i) {
        int idx = tid * 8 + i;
        int a = idx >> 5, kk = idx & 31;
        sM[a][kk] = make_float2(U_re[a * 64 + mcol + kk], U_im[a * 64 + mcol + kk]);
    }
    const float2* inb; float2* outb; size_t outstr;
    if (MODE == 1) {
        inb  = g_H  + ((size_t)b * DD + sl * 32) * DD + nt * 128;
        outb = g_H2 + ((size_t)(b * 64) * 32 + sl) * DD + nt * 128;
        outstr = (size_t)32 * DD;
    } else {
        inb  = g_H2 + ((size_t)(b * 64 + sl)) * 32 * DD + nt * 128;
        outb = g_G  + ((size_t)(b * 64) * 64 + sl) * DD + nt * 128;
        outstr = (size_t)64 * DD;
    }
    {
        int row = tid >> 3, q = tid & 7;
        const float4* src = (const float4*)(inb + (size_t)row * DD);
        float4* dst = (float4*)&sIn[row][0];
#pragma unroll
        for (int i = 0; i < 8; ++i) dst[q + i * 8] = src[q + i * 8];
    }
    __syncthreads();
    const int a0 = (tid >> 5) * 8, c0 = tid & 31;
    u64 acc[8][4];
#pragma unroll
    for (int i = 0; i < 8; ++i)
#pragma unroll
        for (int j = 0; j < 4; ++j) acc[i][j] = 0ull;
#pragma unroll 4
    for (int kk = 0; kk < 32; ++kk) {
        u64 mxx[8], mny[8], hp[4], hs[4];
#pragma unroll
        for (int i = 0; i < 8; ++i) cpack(sM[a0 + i][kk], mxx[i], mny[i]);
        const u64* hrow = (const u64*)&sIn[kk][0];
#pragma unroll
        for (int j = 0; j < 4; ++j) { hp[j] = hrow[c0 + 32 * j]; hs[j] = swp(hp[j]); }
#pragma unroll
        for (int i = 0; i < 8; ++i)
#pragma unroll
            for (int j = 0; j < 4; ++j) {
                fma2(acc[i][j], mxx[i], hp[j]);
                fma2(acc[i][j], mny[i], hs[j]);
            }
    }
#pragma unroll
    for (int i = 0; i < 8; ++i)
#pragma unroll
        for (int j = 0; j < 4; ++j)
            outb[(size_t)(a0 + i) * outstr + c0 + 32 * j] = upk(acc[i][j]);
}

// ---- fused stage 2: per (b,f): T -> Z -> W -> output row, f32x2 core --------
#define S2_SMEM (11424 * 8)
__global__ void __launch_bounds__(256) s2_fused(const float* __restrict__ U_re,
                                                const float* __restrict__ U_im,
                                                float2* __restrict__ out) {
    extern __shared__ float2 dsm[];
    float2* sVp = dsm;            // [64][33] conj(U[a][x])
    float2* sVq = dsm + 2112;     // [64][33] conj(U[a][32+y])
    float2* sT  = dsm + 4224;     // [32][33]
    float2* sZ  = dsm + 5280;     // [32][64]
    float2* sW  = dsm + 7328;     // [64][64]
    const int f = blockIdx.x, b = blockIdx.y, tid = threadIdx.x;
    const int pr = g_pairs[f], j = pr >> 8, k = pr & 255;
    const float sf = (j == k) ? 0.7071067811865476f : 1.f;

    for (int i = tid; i < 2048; i += 256) {
        int a = i >> 5, x = i & 31;
        sVp[a * 33 + x] = make_float2(U_re[a * 64 + x],      -U_im[a * 64 + x]);
        sVq[a * 33 + x] = make_float2(U_re[a * 64 + 32 + x], -U_im[a * 64 + 32 + x]);
    }
    const float2* r1 = g_G + (((size_t)b * 64 + j) * 64 + k) * DD;
    const float2* r2 = g_G + (((size_t)b * 64 + k) * 64 + j) * DD;
    for (int n = tid; n < DD; n += 256) {
        float2 u = r1[n], v = r2[n];
        sT[(n >> 5) * 33 + (n & 31)] = make_float2(sf * (u.x + v.x), sf * (u.y + v.y));
    }
    __syncthreads();

    {   // Z[x][b'] = sum_y T[x][y] * Vq[b'][y]
        const int bp = tid & 63, x0 = (tid >> 6) * 8;
        u64 acc[8];
#pragma unroll
        for (int i = 0; i < 8; ++i) acc[i] = 0ull;
#pragma unroll 4
        for (int y = 0; y < 32; ++y) {
            u64 vxx, vny;
            cpack(sVq[bp * 33 + y], vxx, vny);
#pragma unroll
            for (int i = 0; i < 8; ++i) {
                u64 tp = *(const u64*)&sT[(x0 + i) * 33 + y];
                fma2(acc[i], vxx, tp);
                fma2(acc[i], vny, swp(tp));
            }
        }
#pragma unroll
        for (int i = 0; i < 8; ++i) sZ[(x0 + i) * 64 + bp] = upk(acc[i]);
    }
    __syncthreads();
    {   // W[a'][b'] = sum_x Vp[a'][x] * Z[x][b']
        const int bp = tid & 63, a0 = (tid >> 6) * 16;
        u64 acc[16];
#pragma unroll
        for (int i = 0; i < 16; ++i) acc[i] = 0ull;
#pragma unroll 2
        for (int x = 0; x < 32; ++x) {
            u64 zxx, zny;
            cpack(sZ[x * 64 + bp], zxx, zny);
#pragma unroll
            for (int i = 0; i < 16; ++i) {
                u64 pp = *(const u64*)&sVp[(a0 + i) * 33 + x];
                fma2(acc[i], zxx, pp);
                fma2(acc[i], zny, swp(pp));
            }
        }
#pragma unroll
        for (int i = 0; i < 16; ++i) sW[(a0 + i) * 64 + bp] = upk(acc[i]);
    }
    __syncthreads();
    float2* row = out + ((size_t)b * NF + f) * NF;
    for (int g = tid; g < NF; g += 256) {
        int p2 = g_pairs[g], j2 = p2 >> 8, k2 = p2 & 255;
        float sg = (j2 == k2) ? 0.7071067811865476f : 1.f;
        float2 w1 = sW[j2 * 64 + k2], w2 = sW[k2 * 64 + j2];
        float2 v = make_float2(sg * (w1.x + w2.x), sg * (w1.y + w2.y));
        if (g == f) v.y = 0.f;
        row[g] = v;
    }
}

// ---- launch ------------------------------------------------------------------
extern "C" void kernel_launch(void* const* d_in, const int* in_sizes, int n_in,
                              void* d_out, int out_size) {
    const float* rho_re = (const float*)d_in[0];
    const float* rho_im = (const float*)d_in[1];
    const float* U_re   = (const float*)d_in[2];
    const float* U_im   = (const float*)d_in[3];

    cudaFuncSetAttribute(s2_fused, cudaFuncAttributeMaxDynamicSharedMemorySize, S2_SMEM);

    pairs_init<<<9, 256>>>();
    pack_H<<<dim3(32, 32, NB), dim3(32, 32)>>>(rho_re, rho_im);
    s1_gemm<1><<<dim3(8, 32, NB), 256>>>(U_re, U_im);
    s1_gemm<2><<<dim3(8, 64, NB), 256>>>(U_re, U_im);
    s2_fused<<<dim3(NF, NB), 256, S2_SMEM>>>(U_re, U_im, (float2*)d_out);
}